// round 15
// baseline (speedup 1.0000x reference)
#include <cuda_runtime.h>
#include <cstdint>

#define IN_F   4096
#define OUT_F  11008
#define NG     32           // groups of 128 along K

// ---------- f32x2 packed-math helpers (sm_103a) ----------
static __device__ __forceinline__ uint64_t pack2(float lo, float hi) {
    uint64_t r; asm("mov.b64 %0, {%1,%2};" : "=l"(r) : "f"(lo), "f"(hi)); return r;
}
static __device__ __forceinline__ void unpack2(uint64_t v, float& lo, float& hi) {
    asm("mov.b64 {%0,%1}, %2;" : "=f"(lo), "=f"(hi) : "l"(v));
}
static __device__ __forceinline__ uint64_t fma2(uint64_t a, uint64_t b, uint64_t c) {
    uint64_t d; asm("fma.rn.f32x2 %0, %1, %2, %3;" : "=l"(d) : "l"(a), "l"(b), "l"(c)); return d;
}
static __device__ __forceinline__ uint64_t add2(uint64_t a, uint64_t b) {
    uint64_t d; asm("add.rn.f32x2 %0, %1, %2;" : "=l"(d) : "l"(a), "l"(b)); return d;
}
// Two adjacent nibbles (bits[0:4), bits[4:8)) -> f32x2 {2^23+n0, 2^23+n1}.
// LOP3 does (a & 0xF) | 0x4B000000 in one op (lut 0xEA).
static __device__ __forceinline__ uint64_t nib2(uint32_t q) {
    uint64_t r;
    asm("{\n\t"
        ".reg .b32 lo, hi;\n\t"
        "lop3.b32 lo, %1, 0xF, 0x4B000000, 0xEA;\n\t"
        "shr.u32  hi, %1, 4;\n\t"
        "lop3.b32 hi, hi, 0xF, 0x4B000000, 0xEA;\n\t"
        "mov.b64  %0, {lo, hi};\n\t"
        "}" : "=l"(r) : "r"(q));
    return r;
}

// Block tile: 32 rows (m) x 32 cols (n), 128 threads.
// Thread tile: TM=4 rows x TN=2 cols, k processed in f32x2 pairs.
// Per group g: accumulate integer-domain (w - z) dot in ag[], then one
// fused scale fold acc += s * ag  (avoids per-weight scale FMA AND avoids
// the catastrophic-cancellation magic-constant fold).
__global__ void __launch_bounds__(128, 4)
qlinear_kernel(const float* __restrict__ x,
               const int*   __restrict__ qweight,   // [IN_F/8, OUT_F]
               const int*   __restrict__ qzeros,    // [NG, OUT_F/8]
               const float* __restrict__ scales,    // [NG, OUT_F]
               const float* __restrict__ bias,      // [OUT_F]
               float*       __restrict__ out)       // [64, OUT_F]
{
    const int tid = threadIdx.x;
    const int n   = blockIdx.x * 32 + (tid & 15) * 2;   // 2 consecutive cols
    const int m0  = blockIdx.y * 32 + (tid >> 4) * 4;   // 4 consecutive rows

    const float* xb = x + (size_t)m0 * IN_F;

    uint64_t acc[4][2];
#pragma unroll
    for (int r = 0; r < 4; r++) { acc[r][0] = 0ull; acc[r][1] = 0ull; }

    for (int g = 0; g < NG; g++) {
        // Per-group, per-column constants.
        // nC2 = -(2^23 + z + 1): subtracting it from (2^23 + q) is EXACT
        // (both near 2^23, small integer difference -> Sterbenz).
        uint64_t s2[2], nC2[2];
#pragma unroll
        for (int c = 0; c < 2; c++) {
            const int nn = n + c;
            const float s = __ldg(scales + g * OUT_F + nn);
            const uint32_t qz =
                (((uint32_t)__ldg(qzeros + g * (OUT_F / 8) + (nn >> 3))) >> (4 * (nn & 7))) & 15u;
            const float negC = -(8388608.0f + (float)(qz + 1u));
            s2[c]  = pack2(s, s);
            nC2[c] = pack2(negC, negC);
        }

        uint64_t ag[4][2];
#pragma unroll
        for (int r = 0; r < 4; r++) { ag[r][0] = 0ull; ag[r][1] = 0ull; }

        const int*   qwp = qweight + (size_t)(g * 16) * OUT_F + n;
        const float* xg  = xb + g * 128;

#pragma unroll 4
        for (int i = 0; i < 16; i++) {          // 16 packed rows = 128 k
            const uint2  qw = __ldg((const uint2*)(qwp + (size_t)i * OUT_F)); // 2 cols
            const float* xi = xg + i * 8;       // 8 k values per packed row
#pragma unroll
            for (int h = 0; h < 2; h++) {       // 4 k per half
                const uint32_t q0 = h ? (qw.x >> 16) : qw.x;
                const uint32_t q1 = h ? (qw.y >> 16) : qw.y;
                // (w - zero) pairs in exact fp32 integer domain
                const uint64_t wA0 = add2(nib2(q0),      nC2[0]); // k+0,k+1 col0
                const uint64_t wB0 = add2(nib2(q0 >> 8), nC2[0]); // k+2,k+3 col0
                const uint64_t wA1 = add2(nib2(q1),      nC2[1]);
                const uint64_t wB1 = add2(nib2(q1 >> 8), nC2[1]);
                const float* xh = xi + h * 4;
#pragma unroll
                for (int r = 0; r < 4; r++) {
                    const float4 xv = __ldg((const float4*)(xh + (size_t)r * IN_F));
                    const uint64_t xa = pack2(xv.x, xv.y);
                    const uint64_t xc = pack2(xv.z, xv.w);
                    ag[r][0] = fma2(xa, wA0, ag[r][0]);
                    ag[r][1] = fma2(xa, wA1, ag[r][1]);
                    ag[r][0] = fma2(xc, wB0, ag[r][0]);
                    ag[r][1] = fma2(xc, wB1, ag[r][1]);
                }
            }
        }

        // Fold group: acc += scale * ag  (one FFMA2 per accumulator per group)
#pragma unroll
        for (int r = 0; r < 4; r++) {
            acc[r][0] = fma2(s2[0], ag[r][0], acc[r][0]);
            acc[r][1] = fma2(s2[1], ag[r][1], acc[r][1]);
        }
    }

    // Epilogue: combine even/odd-k halves, add bias, store float2.
    const float b0 = __ldg(bias + n);
    const float b1 = __ldg(bias + n + 1);
#pragma unroll
    for (int r = 0; r < 4; r++) {
        float l0, h0, l1, h1;
        unpack2(acc[r][0], l0, h0);
        unpack2(acc[r][1], l1, h1);
        float2 o = make_float2(l0 + h0 + b0, l1 + h1 + b1);
        *(float2*)(out + (size_t)(m0 + r) * OUT_F + n) = o;
    }
}

extern "C" void kernel_launch(void* const* d_in, const int* in_sizes, int n_in,
                              void* d_out, int out_size)
{
    // metadata order: x, qweight, qzeros, scales, g_idx (unused: contiguous
    // groups, g_idx = k // 128), bias
    const float* x       = (const float*)d_in[0];
    const int*   qweight = (const int*)  d_in[1];
    const int*   qzeros  = (const int*)  d_in[2];
    const float* scales  = (const float*)d_in[3];
    const float* bias    = (const float*)d_in[5];
    float*       out     = (float*)d_out;

    dim3 grid(OUT_F / 32, 2);   // 344 n-tiles x 2 m-halves = 688 blocks
    qlinear_kernel<<<grid, 128>>>(x, qweight, qzeros, scales, bias, out);
}

// round 16
// speedup vs baseline: 1.0011x; 1.0011x over previous
#include <cuda_runtime.h>
#include <cstdint>

#define IN_F   4096
#define OUT_F  11008
#define NG     32           // groups of 128 along K

// ---------- f32x2 packed-math helpers (sm_103a) ----------
static __device__ __forceinline__ uint64_t pack2(float lo, float hi) {
    uint64_t r; asm("mov.b64 %0, {%1,%2};" : "=l"(r) : "f"(lo), "f"(hi)); return r;
}
static __device__ __forceinline__ void unpack2(uint64_t v, float& lo, float& hi) {
    asm("mov.b64 {%0,%1}, %2;" : "=f"(lo), "=f"(hi) : "l"(v));
}
static __device__ __forceinline__ uint64_t fma2(uint64_t a, uint64_t b, uint64_t c) {
    uint64_t d; asm("fma.rn.f32x2 %0, %1, %2, %3;" : "=l"(d) : "l"(a), "l"(b), "l"(c)); return d;
}
static __device__ __forceinline__ uint64_t add2(uint64_t a, uint64_t b) {
    uint64_t d; asm("add.rn.f32x2 %0, %1, %2;" : "=l"(d) : "l"(a), "l"(b)); return d;
}
// Two adjacent nibbles (bits[0:4), bits[4:8)) -> f32x2 {2^23+n0, 2^23+n1}.
// LOP3 does (a & 0xF) | 0x4B000000 in one op (lut 0xEA).
static __device__ __forceinline__ uint64_t nib2(uint32_t q) {
    uint64_t r;
    asm("{\n\t"
        ".reg .b32 lo, hi;\n\t"
        "lop3.b32 lo, %1, 0xF, 0x4B000000, 0xEA;\n\t"
        "shr.u32  hi, %1, 4;\n\t"
        "lop3.b32 hi, hi, 0xF, 0x4B000000, 0xEA;\n\t"
        "mov.b64  %0, {lo, hi};\n\t"
        "}" : "=l"(r) : "r"(q));
    return r;
}

// Block tile: 32 rows (m) x 32 cols (n), 128 threads.
// Thread tile: TM=4 rows x TN=2 cols, k processed in f32x2 pairs.
// Per group g: accumulate integer-domain (w - z) dot in ag[], then one
// fused scale fold acc += s * ag  (avoids per-weight scale FMA AND avoids
// the catastrophic-cancellation magic-constant fold).
__global__ void __launch_bounds__(128, 4)
qlinear_kernel(const float* __restrict__ x,
               const int*   __restrict__ qweight,   // [IN_F/8, OUT_F]
               const int*   __restrict__ qzeros,    // [NG, OUT_F/8]
               const float* __restrict__ scales,    // [NG, OUT_F]
               const float* __restrict__ bias,      // [OUT_F]
               float*       __restrict__ out)       // [64, OUT_F]
{
    const int tid = threadIdx.x;
    const int n   = blockIdx.x * 32 + (tid & 15) * 2;   // 2 consecutive cols
    const int m0  = blockIdx.y * 32 + (tid >> 4) * 4;   // 4 consecutive rows

    const float* xb = x + (size_t)m0 * IN_F;

    uint64_t acc[4][2];
#pragma unroll
    for (int r = 0; r < 4; r++) { acc[r][0] = 0ull; acc[r][1] = 0ull; }

    for (int g = 0; g < NG; g++) {
        // Per-group, per-column constants.
        // nC2 = -(2^23 + z + 1): subtracting it from (2^23 + q) is EXACT
        // (both near 2^23, small integer difference -> Sterbenz).
        uint64_t s2[2], nC2[2];
#pragma unroll
        for (int c = 0; c < 2; c++) {
            const int nn = n + c;
            const float s = __ldg(scales + g * OUT_F + nn);
            const uint32_t qz =
                (((uint32_t)__ldg(qzeros + g * (OUT_F / 8) + (nn >> 3))) >> (4 * (nn & 7))) & 15u;
            const float negC = -(8388608.0f + (float)(qz + 1u));
            s2[c]  = pack2(s, s);
            nC2[c] = pack2(negC, negC);
        }

        uint64_t ag[4][2];
#pragma unroll
        for (int r = 0; r < 4; r++) { ag[r][0] = 0ull; ag[r][1] = 0ull; }

        const int*   qwp = qweight + (size_t)(g * 16) * OUT_F + n;
        const float* xg  = xb + g * 128;

#pragma unroll 4
        for (int i = 0; i < 16; i++) {          // 16 packed rows = 128 k
            const uint2  qw = __ldg((const uint2*)(qwp + (size_t)i * OUT_F)); // 2 cols
            const float* xi = xg + i * 8;       // 8 k values per packed row
#pragma unroll
            for (int h = 0; h < 2; h++) {       // 4 k per half
                const uint32_t q0 = h ? (qw.x >> 16) : qw.x;
                const uint32_t q1 = h ? (qw.y >> 16) : qw.y;
                // (w - zero) pairs in exact fp32 integer domain
                const uint64_t wA0 = add2(nib2(q0),      nC2[0]); // k+0,k+1 col0
                const uint64_t wB0 = add2(nib2(q0 >> 8), nC2[0]); // k+2,k+3 col0
                const uint64_t wA1 = add2(nib2(q1),      nC2[1]);
                const uint64_t wB1 = add2(nib2(q1 >> 8), nC2[1]);
                const float* xh = xi + h * 4;
#pragma unroll
                for (int r = 0; r < 4; r++) {
                    const float4 xv = __ldg((const float4*)(xh + (size_t)r * IN_F));
                    const uint64_t xa = pack2(xv.x, xv.y);
                    const uint64_t xc = pack2(xv.z, xv.w);
                    ag[r][0] = fma2(xa, wA0, ag[r][0]);
                    ag[r][1] = fma2(xa, wA1, ag[r][1]);
                    ag[r][0] = fma2(xc, wB0, ag[r][0]);
                    ag[r][1] = fma2(xc, wB1, ag[r][1]);
                }
            }
        }

        // Fold group: acc += scale * ag  (one FFMA2 per accumulator per group)
#pragma unroll
        for (int r = 0; r < 4; r++) {
            acc[r][0] = fma2(s2[0], ag[r][0], acc[r][0]);
            acc[r][1] = fma2(s2[1], ag[r][1], acc[r][1]);
        }
    }

    // Epilogue: combine even/odd-k halves, add bias, store float2.
    const float b0 = __ldg(bias + n);
    const float b1 = __ldg(bias + n + 1);
#pragma unroll
    for (int r = 0; r < 4; r++) {
        float l0, h0, l1, h1;
        unpack2(acc[r][0], l0, h0);
        unpack2(acc[r][1], l1, h1);
        float2 o = make_float2(l0 + h0 + b0, l1 + h1 + b1);
        *(float2*)(out + (size_t)(m0 + r) * OUT_F + n) = o;
    }
}

extern "C" void kernel_launch(void* const* d_in, const int* in_sizes, int n_in,
                              void* d_out, int out_size)
{
    // metadata order: x, qweight, qzeros, scales, g_idx (unused: contiguous
    // groups, g_idx = k // 128), bias
    const float* x       = (const float*)d_in[0];
    const int*   qweight = (const int*)  d_in[1];
    const int*   qzeros  = (const int*)  d_in[2];
    const float* scales  = (const float*)d_in[3];
    const float* bias    = (const float*)d_in[5];
    float*       out     = (float*)d_out;

    dim3 grid(OUT_F / 32, 2);   // 344 n-tiles x 2 m-halves = 688 blocks
    qlinear_kernel<<<grid, 128>>>(x, qweight, qzeros, scales, bias, out);
}